// round 4
// baseline (speedup 1.0000x reference)
#include <cuda_runtime.h>
#include <cstdint>
#include <cstddef>

namespace {
constexpr int S_DIM = 2048, R_DIM = 384, CE = 64;
constexpr int NTHR = 512, RPT = 4;          // phase A rows/thread
constexpr int CHUNK = 256, NCH = 8;         // phase D chunks (double buffered)

// ---- shared layout (float offsets) ----
// union [0, 53248):
//   A/C: kbuf u64[4][2048] @u64 0, vbuf @u64 8192 (fl 0..32768)
//        scalars: wk@33024, wv@33536, qvec@34048, qh@34112, red@34176, max@35328
//   D:   wg_u u64[64*80] fl 0..10240, wo_u fl 10240..20480
//        xnT buffers: XNT0 fl 20480..36864, XNT1 fl 36864..53248
constexpr int OFF_WK = 33024, OFF_WV = 33536, OFF_QVEC = 34048, OFF_QH = 34112;
constexpr int OFF_RED = 34176, OFF_MAX = 35328;
constexpr int XNT0 = 20480, XNT_SZ = 16384;
constexpr int WD = 80;                      // u64 stride per dup-weight row
// persistent:
constexpr int OFF_MU = 53248, OFF_RS = 55296, OFF_LNW = 57344, OFF_LNB = 57408;
constexpr int OFF_BGD = 57472, OFF_BOD = 57600, OFF_OSH = 57728;
constexpr int SMEM_FL = 57792;
constexpr size_t SMEM_BYTES = (size_t)SMEM_FL * 4;   // 231168 B (fits, proven R3)
}

struct alignas(16) u64x2 { unsigned long long a, b; };

__device__ __forceinline__ unsigned long long pack2(float x) {
    unsigned long long r;
    asm("mov.b64 %0, {%1, %2};" : "=l"(r) : "f"(x), "f"(x));
    return r;
}
__device__ __forceinline__ unsigned long long packAB(float a, float b) {
    unsigned long long r;
    asm("mov.b64 %0, {%1, %2};" : "=l"(r) : "f"(a), "f"(b));
    return r;
}
__device__ __forceinline__ float2 unpack2(unsigned long long v) {
    float2 f;
    asm("mov.b64 {%0, %1}, %2;" : "=f"(f.x), "=f"(f.y) : "l"(v));
    return f;
}
__device__ __forceinline__ void ffma2(unsigned long long& d,
                                      unsigned long long a, unsigned long long b) {
    asm("fma.rn.f32x2 %0, %1, %2, %0;" : "+l"(d) : "l"(a), "l"(b));
}
__device__ __forceinline__ unsigned long long addf2(unsigned long long a,
                                                    unsigned long long b) {
    unsigned long long r;
    asm("add.rn.f32x2 %0, %1, %2;" : "=l"(r) : "l"(a), "l"(b));
    return r;
}

// register-tiled f32x2 GEMM: out[2 row-pairs][8 cols] over 64-dim contraction.
// xb: [64 c][256 rows] XOR-swizzled, wtab: dup-pair table stride WD.
__device__ __forceinline__ void gemm64(const float* __restrict__ xb_base,
                                       const unsigned long long* __restrict__ wtab,
                                       const unsigned long long* __restrict__ bias,
                                       int R0, int cg,
                                       unsigned long long acc[2][8])
{
    #pragma unroll
    for (int j = 0; j < 2; ++j)
        #pragma unroll
        for (int cc = 0; cc < 8; ++cc) acc[j][cc] = bias[cg * 8 + cc];

    #pragma unroll 2
    for (int c4 = 0; c4 < 16; ++c4) {
        const int sw = 2 * c4;
        const int i0 = R0 ^ sw;
        const int i1 = i0 ^ 2;
        const float* xb = xb_base + c4 * 4 * 256;
        const unsigned long long* wr = wtab + c4 * 4 * WD + cg * 10;
        #pragma unroll
        for (int ci = 0; ci < 4; ++ci) {
            unsigned long long x0 =
                *reinterpret_cast<const unsigned long long*>(xb + ci * 256 + i0);
            unsigned long long x1 =
                *reinterpret_cast<const unsigned long long*>(xb + ci * 256 + i1);
            const u64x2* wp = reinterpret_cast<const u64x2*>(wr + ci * WD);
            u64x2 w0 = wp[0], w1 = wp[1], w2 = wp[2], w3 = wp[3];
            ffma2(acc[0][0], x0, w0.a); ffma2(acc[0][1], x0, w0.b);
            ffma2(acc[0][2], x0, w1.a); ffma2(acc[0][3], x0, w1.b);
            ffma2(acc[0][4], x0, w2.a); ffma2(acc[0][5], x0, w2.b);
            ffma2(acc[0][6], x0, w3.a); ffma2(acc[0][7], x0, w3.b);
            ffma2(acc[1][0], x1, w0.a); ffma2(acc[1][1], x1, w0.b);
            ffma2(acc[1][2], x1, w1.a); ffma2(acc[1][3], x1, w1.b);
            ffma2(acc[1][4], x1, w2.a); ffma2(acc[1][5], x1, w2.b);
            ffma2(acc[1][6], x1, w3.a); ffma2(acc[1][7], x1, w3.b);
        }
    }
}

__global__ void __launch_bounds__(NTHR, 1)
msa_kernel(const float* __restrict__ m,    const float* __restrict__ mask,
           const float* __restrict__ ln_w, const float* __restrict__ ln_b,
           const float* __restrict__ wq,   const float* __restrict__ wk,
           const float* __restrict__ wv,   const float* __restrict__ wg,
           const float* __restrict__ bg,   const float* __restrict__ wo,
           const float* __restrict__ bo,   float* __restrict__ out)
{
    extern __shared__ float smf[];
    unsigned long long* kbuf_u = reinterpret_cast<unsigned long long*>(smf);
    unsigned long long* vbuf_u = kbuf_u + 4 * S_DIM;
    unsigned long long* wg_u   = reinterpret_cast<unsigned long long*>(smf);
    unsigned long long* wo_u   = wg_u + 64 * WD;
    float* wk_s  = smf + OFF_WK;
    float* wv_s  = smf + OFF_WV;
    float* qvec_s= smf + OFF_QVEC;
    float* qh_s  = smf + OFF_QH;
    float* red   = smf + OFF_RED;
    float* max_sh= smf + OFF_MAX;
    float* mu_s  = smf + OFF_MU;
    float* rs_s  = smf + OFF_RS;
    float* lnw_s = smf + OFF_LNW;
    float* lnb_s = smf + OFF_LNB;
    unsigned long long* bgd = reinterpret_cast<unsigned long long*>(smf + OFF_BGD);
    unsigned long long* bod = reinterpret_cast<unsigned long long*>(smf + OFF_BOD);
    float* o_sh  = smf + OFF_OSH;

    const int tid  = threadIdx.x;
    const int r    = blockIdx.x;
    const int lane = tid & 31;
    const int wid  = tid >> 5;

    for (int i = tid; i < 512; i += NTHR) { wk_s[i] = wk[i]; wv_s[i] = wv[i]; }
    if (tid < 64) { lnw_s[tid] = ln_w[tid]; lnb_s[tid] = ln_b[tid]; }
    __syncthreads();

    // ============== Phase A: LN stats + k/v projections + masked qsum ======
    unsigned long long qsum2[32];
    #pragma unroll
    for (int t = 0; t < 32; ++t) qsum2[t] = 0ull;
    float msum = 0.f;

    #pragma unroll 1
    for (int i = 0; i < RPT; ++i) {
        const int s = tid + NTHR * i;
        const float4* xr = reinterpret_cast<const float4*>(m + ((size_t)s * R_DIM + r) * CE);
        float sum = 0.f, sq = 0.f;
        #pragma unroll
        for (int t = 0; t < 16; ++t) {
            float4 v = __ldg(xr + t);
            sum += v.x + v.y + v.z + v.w;
            sq = fmaf(v.x, v.x, sq); sq = fmaf(v.y, v.y, sq);
            sq = fmaf(v.z, v.z, sq); sq = fmaf(v.w, v.w, sq);
        }
        const float muv  = sum * (1.f / CE);
        const float var  = sq * (1.f / CE) - muv * muv;
        const float rstd = rsqrtf(var + 1e-5f);
        const float mk   = __ldg(mask + (size_t)s * R_DIM + r);
        mu_s[s] = muv; rs_s[s] = rstd; msum += mk;
        const unsigned long long mk2 = pack2(mk);

        unsigned long long ka[4], va[4];
        #pragma unroll
        for (int t = 0; t < 4; ++t) { ka[t] = 0ull; va[t] = 0ull; }

        #pragma unroll
        for (int t = 0; t < 16; ++t) {
            float4 v  = __ldg(xr + t);
            float4 lw = reinterpret_cast<const float4*>(lnw_s)[t];
            float4 lb = reinterpret_cast<const float4*>(lnb_s)[t];
            float xn0 = (v.x - muv) * rstd * lw.x + lb.x;
            float xn1 = (v.y - muv) * rstd * lw.y + lb.y;
            float xn2 = (v.z - muv) * rstd * lw.z + lb.z;
            float xn3 = (v.w - muv) * rstd * lw.w + lb.w;
            ffma2(qsum2[2*t],   packAB(xn0, xn1), mk2);
            ffma2(qsum2[2*t+1], packAB(xn2, xn3), mk2);
            const float xnv[4] = {xn0, xn1, xn2, xn3};
            #pragma unroll
            for (int j = 0; j < 4; ++j) {
                const int c = 4*t + j;
                const unsigned long long xx = pack2(xnv[j]);
                u64x2 k0 = reinterpret_cast<const u64x2*>(wk_s + c * 8)[0];
                u64x2 v0 = reinterpret_cast<const u64x2*>(wv_s + c * 8)[0];
                u64x2 k1 = reinterpret_cast<const u64x2*>(wk_s + c * 8)[1];
                u64x2 v1 = reinterpret_cast<const u64x2*>(wv_s + c * 8)[1];
                ffma2(ka[0], xx, k0.a); ffma2(ka[1], xx, k0.b);
                ffma2(ka[2], xx, k1.a); ffma2(ka[3], xx, k1.b);
                ffma2(va[0], xx, v0.a); ffma2(va[1], xx, v0.b);
                ffma2(va[2], xx, v1.a); ffma2(va[3], xx, v1.b);
            }
        }
        #pragma unroll
        for (int t = 0; t < 4; ++t) {
            kbuf_u[t * S_DIM + s] = ka[t];
            vbuf_u[t * S_DIM + s] = va[t];
        }
    }

    #pragma unroll
    for (int t = 0; t < 32; ++t) {
        #pragma unroll
        for (int o = 16; o > 0; o >>= 1)
            qsum2[t] = addf2(qsum2[t], __shfl_xor_sync(0xffffffffu, qsum2[t], o));
    }
    #pragma unroll
    for (int o = 16; o > 0; o >>= 1)
        msum += __shfl_xor_sync(0xffffffffu, msum, o);
    if (lane == 0) {
        #pragma unroll
        for (int t = 0; t < 32; ++t) {
            float2 p = unpack2(qsum2[t]);
            red[wid * 72 + 2*t] = p.x; red[wid * 72 + 2*t+1] = p.y;
        }
        red[wid * 72 + 64] = msum;
    }
    __syncthreads();

    if (tid < 64) {
        float t0 = 0.f, ms = 0.f;
        #pragma unroll
        for (int w = 0; w < 16; ++w) { t0 += red[w * 72 + tid]; ms += red[w * 72 + 64]; }
        qvec_s[tid] = t0 * __fdividef(1.f, ms + 1e-10f);
    }
    __syncthreads();
    if (tid < 64) {
        float acc = 0.f;
        #pragma unroll 8
        for (int c = 0; c < CE; ++c) acc = fmaf(qvec_s[c], __ldg(wq + c * 64 + tid), acc);
        qh_s[tid] = acc * 0.3535533905932738f;
    }
    __syncthreads();

    // ============== Phase C: scores / softmax / o ==========================
    {
        float sc[RPT][8], mh[8];
        #pragma unroll
        for (int h = 0; h < 8; ++h) mh[h] = -1e30f;

        #pragma unroll
        for (int i = 0; i < RPT; ++i) {
            const int s = tid + NTHR * i;
            unsigned long long kk[4];
            #pragma unroll
            for (int j = 0; j < 4; ++j) kk[j] = kbuf_u[j * S_DIM + s];
            const float bias = 1e9f * (__ldg(mask + (size_t)s * R_DIM + r) - 1.f);
            #pragma unroll
            for (int h = 0; h < 8; ++h) {
                unsigned long long acc = 0ull;
                #pragma unroll
                for (int j = 0; j < 4; ++j) {
                    unsigned long long q2 =
                        reinterpret_cast<const unsigned long long*>(qh_s)[h*4+j];
                    ffma2(acc, q2, kk[j]);
                }
                float2 p = unpack2(acc);
                float a = bias + p.x + p.y;
                sc[i][h] = a;
                mh[h] = fmaxf(mh[h], a);
            }
        }
        #pragma unroll
        for (int h = 0; h < 8; ++h) {
            #pragma unroll
            for (int o = 16; o > 0; o >>= 1)
                mh[h] = fmaxf(mh[h], __shfl_xor_sync(0xffffffffu, mh[h], o));
        }
        if (lane == 0) {
            #pragma unroll
            for (int h = 0; h < 8; ++h) red[wid * 72 + h] = mh[h];
        }
        __syncthreads();
        if (tid < 8) {
            float mm = -1e30f;
            #pragma unroll
            for (int w = 0; w < 16; ++w) mm = fmaxf(mm, red[w * 72 + tid]);
            max_sh[tid] = mm;
        }
        __syncthreads();

        #pragma unroll 1
        for (int hb = 0; hb < 2; ++hb) {
            unsigned long long oacc2[16];
            float sumh[4];
            #pragma unroll
            for (int t = 0; t < 16; ++t) oacc2[t] = 0ull;
            #pragma unroll
            for (int h = 0; h < 4; ++h) sumh[h] = 0.f;

            #pragma unroll
            for (int i = 0; i < RPT; ++i) {
                const int s = tid + NTHR * i;
                unsigned long long vv[4];
                #pragma unroll
                for (int j = 0; j < 4; ++j) vv[j] = vbuf_u[j * S_DIM + s];
                #pragma unroll
                for (int h = 0; h < 4; ++h) {
                    const int hh = hb * 4 + h;
                    const float e = __expf(sc[i][hh] - max_sh[hh]);
                    sumh[h] += e;
                    const unsigned long long e2 = pack2(e);
                    #pragma unroll
                    for (int j = 0; j < 4; ++j) ffma2(oacc2[h*4+j], e2, vv[j]);
                }
            }
            #pragma unroll
            for (int t = 0; t < 16; ++t) {
                #pragma unroll
                for (int o = 16; o > 0; o >>= 1)
                    oacc2[t] = addf2(oacc2[t], __shfl_xor_sync(0xffffffffu, oacc2[t], o));
            }
            #pragma unroll
            for (int h = 0; h < 4; ++h) {
                #pragma unroll
                for (int o = 16; o > 0; o >>= 1)
                    sumh[h] += __shfl_xor_sync(0xffffffffu, sumh[h], o);
            }
            if (lane == 0) {
                #pragma unroll
                for (int t = 0; t < 16; ++t) {
                    float2 p = unpack2(oacc2[t]);
                    red[wid * 72 + hb*32 + 2*t]   = p.x;
                    red[wid * 72 + hb*32 + 2*t+1] = p.y;
                }
                #pragma unroll
                for (int h = 0; h < 4; ++h) red[wid * 72 + 64 + hb*4 + h] = sumh[h];
            }
            __syncthreads();
        }
        if (tid < 64) {
            float t0 = 0.f, ss = 0.f;
            #pragma unroll
            for (int w = 0; w < 16; ++w) {
                t0 += red[w * 72 + tid];
                ss += red[w * 72 + 64 + (tid >> 3)];
            }
            o_sh[tid] = __fdividef(t0, ss);
        }
        __syncthreads();
    }

    // ============== Phase D: double-buffered gate + output GEMMs ===========
    // dup-pair weight tables: row c, 8 groups of (8 data + 2 pad) u64
    for (int idx = tid; idx < 4096; idx += NTHR) {
        const int c = idx >> 6, col = idx & 63;
        const int dst = c * WD + (col >> 3) * 10 + (col & 7);
        wg_u[dst] = pack2(__ldg(wg + idx));
        wo_u[dst] = pack2(__ldg(wo + idx));
    }
    if (tid < 64) { bgd[tid] = pack2(__ldg(bg + tid)); bod[tid] = pack2(__ldg(bo + tid)); }

    const int cg = tid & 7;
    const int rg = tid >> 3;
    const int R0 = rg * 4;           // 4 rows per thread, 256-row chunk
    const int c4l  = tid & 15;       // loader column-quad
    const int rw0  = tid >> 4;       // loader base row
    const float4 lwv = reinterpret_cast<const float4*>(lnw_s)[c4l];
    const float4 lbv = reinterpret_cast<const float4*>(lnb_s)[c4l];
    const size_t mstep = (size_t)32 * R_DIM * CE / 4;   // float4s per 32 rows

    // prologue: load chunk 0 into buffer 0
    {
        const float4* src = reinterpret_cast<const float4*>(
            m + ((size_t)rw0 * R_DIM + r) * CE) + c4l;
        float* dst = smf + XNT0;
        #pragma unroll
        for (int k = 0; k < 8; ++k) {
            float4 v = __ldg(src + mstep * k);
            const int row = rw0 + 32 * k;
            const float muv = mu_s[row], rsv = rs_s[row];
            const int rw = row ^ (2 * c4l);
            dst[(4*c4l+0) * 256 + rw] = (v.x - muv) * rsv * lwv.x + lbv.x;
            dst[(4*c4l+1) * 256 + rw] = (v.y - muv) * rsv * lwv.y + lbv.y;
            dst[(4*c4l+2) * 256 + rw] = (v.z - muv) * rsv * lwv.z + lbv.z;
            dst[(4*c4l+3) * 256 + rw] = (v.w - muv) * rsv * lwv.w + lbv.w;
        }
    }
    __syncthreads();

    #pragma unroll 1
    for (int ch = 0; ch < NCH; ++ch) {
        const int S0 = ch * CHUNK;
        const int p  = ch & 1;
        float* cur = smf + XNT0 + p * XNT_SZ;
        float* nxt = smf + XNT0 + (p ^ 1) * XNT_SZ;

        // prefetch next chunk (latency hidden behind GEMM1)
        float4 pf[8];
        if (ch + 1 < NCH) {
            const float4* src = reinterpret_cast<const float4*>(
                m + ((size_t)(S0 + CHUNK + rw0) * R_DIM + r) * CE) + c4l;
            #pragma unroll
            for (int k = 0; k < 8; ++k) pf[k] = __ldg(src + mstep * k);
        }

        // GEMM1: gate = xn @ wg + bg
        unsigned long long acc[2][8];
        gemm64(cur, wg_u, bgd, R0, cg, acc);
        __syncthreads();

        // sigmoid * o -> gg, overwrite cur (transposed, same swizzle)
        #pragma unroll
        for (int cc = 0; cc < 8; ++cc) {
            const int col = cg * 8 + cc;
            const float osv = o_sh[col];
            float* gb = cur + col * 256;
            const int sw = (col >> 2) << 1;
            #pragma unroll
            for (int j = 0; j < 2; ++j) {
                float2 p2 = unpack2(acc[j][cc]);
                const float g0 = osv * __fdividef(1.f, 1.f + __expf(-p2.x));
                const float g1 = osv * __fdividef(1.f, 1.f + __expf(-p2.y));
                *reinterpret_cast<unsigned long long*>(gb + ((R0 + 2*j) ^ sw)) =
                    packAB(g0, g1);
            }
        }

        // store prefetched chunk into the other buffer
        if (ch + 1 < NCH) {
            #pragma unroll
            for (int k = 0; k < 8; ++k) {
                const int row = rw0 + 32 * k;
                const float muv = mu_s[S0 + CHUNK + row];
                const float rsv = rs_s[S0 + CHUNK + row];
                const int rw = row ^ (2 * c4l);
                nxt[(4*c4l+0) * 256 + rw] = (pf[k].x - muv) * rsv * lwv.x + lbv.x;
                nxt[(4*c4l+1) * 256 + rw] = (pf[k].y - muv) * rsv * lwv.y + lbv.y;
                nxt[(4*c4l+2) * 256 + rw] = (pf[k].z - muv) * rsv * lwv.z + lbv.z;
                nxt[(4*c4l+3) * 256 + rw] = (pf[k].w - muv) * rsv * lwv.w + lbv.w;
            }
        }
        __syncthreads();

        // GEMM2: out = gg @ wo + bo
        unsigned long long acc2[2][8];
        gemm64(cur, wo_u, bod, R0, cg, acc2);

        #pragma unroll
        for (int j = 0; j < 2; ++j) {
            float lo[8], hi[8];
            #pragma unroll
            for (int cc = 0; cc < 8; ++cc) {
                float2 p2 = unpack2(acc2[j][cc]);
                lo[cc] = p2.x; hi[cc] = p2.y;
            }
            const int s0 = S0 + R0 + 2*j;
            float* o0 = out + ((size_t)s0 * R_DIM + r) * CE + cg * 8;
            float* o1 = o0 + (size_t)R_DIM * CE;
            reinterpret_cast<float4*>(o0)[0] = make_float4(lo[0], lo[1], lo[2], lo[3]);
            reinterpret_cast<float4*>(o0)[1] = make_float4(lo[4], lo[5], lo[6], lo[7]);
            reinterpret_cast<float4*>(o1)[0] = make_float4(hi[0], hi[1], hi[2], hi[3]);
            reinterpret_cast<float4*>(o1)[1] = make_float4(hi[4], hi[5], hi[6], hi[7]);
        }
    }
}

extern "C" void kernel_launch(void* const* d_in, const int* in_sizes, int n_in,
                              void* d_out, int out_size)
{
    (void)in_sizes; (void)n_in; (void)out_size;
    cudaFuncSetAttribute(msa_kernel,
                         cudaFuncAttributeMaxDynamicSharedMemorySize, (int)SMEM_BYTES);
    msa_kernel<<<R_DIM, NTHR, SMEM_BYTES>>>(
        (const float*)d_in[0], (const float*)d_in[1], (const float*)d_in[2],
        (const float*)d_in[3], (const float*)d_in[4], (const float*)d_in[5],
        (const float*)d_in[6], (const float*)d_in[7], (const float*)d_in[8],
        (const float*)d_in[9], (const float*)d_in[10], (float*)d_out);
}

// round 5
// speedup vs baseline: 1.0094x; 1.0094x over previous
#include <cuda_runtime.h>
#include <cstdint>
#include <cstddef>

namespace {
constexpr int S_DIM = 2048, R_DIM = 384, CE = 64;
// ---- K1 (phases A+C): 512 threads ----
constexpr int NTHR1 = 512, RPT = 4;
constexpr int OFF_WK = 33024, OFF_WV = 33536, OFF_QVEC = 34048, OFF_QH = 34112;
constexpr int OFF_RED = 34176, OFF_MAX = 35328;
constexpr int SMEM1_FL = 35344;
constexpr size_t SMEM1_BYTES = (size_t)SMEM1_FL * 4;    // ~141 KB
// ---- K2 (phase D): 1024 threads ----
constexpr int NTHR2 = 1024, CHUNK = 512, NCH = 4;
constexpr int WD = 80;                                   // u64 per dup-weight row
constexpr int K2_XNT = 20480;                            // fl offset
constexpr int K2_LNW = 53248, K2_LNB = 53312, K2_BGD = 53376, K2_BOD = 53504;
constexpr int K2_OSH = 53632;
constexpr int SMEM2_FL = 53696;
constexpr size_t SMEM2_BYTES = (size_t)SMEM2_FL * 4;    // ~210 KB
}

// global scratch (allowed: __device__ arrays)
__device__ float2 g_stat[(size_t)R_DIM * S_DIM];         // (mu, rstd) per (r, s)
__device__ float  g_osh[(size_t)R_DIM * CE];             // o_flat per column

struct alignas(16) u64x2 { unsigned long long a, b; };

__device__ __forceinline__ unsigned long long pack2(float x) {
    unsigned long long r;
    asm("mov.b64 %0, {%1, %2};" : "=l"(r) : "f"(x), "f"(x));
    return r;
}
__device__ __forceinline__ unsigned long long packAB(float a, float b) {
    unsigned long long r;
    asm("mov.b64 %0, {%1, %2};" : "=l"(r) : "f"(a), "f"(b));
    return r;
}
__device__ __forceinline__ float2 unpack2(unsigned long long v) {
    float2 f;
    asm("mov.b64 {%0, %1}, %2;" : "=f"(f.x), "=f"(f.y) : "l"(v));
    return f;
}
__device__ __forceinline__ void ffma2(unsigned long long& d,
                                      unsigned long long a, unsigned long long b) {
    asm("fma.rn.f32x2 %0, %1, %2, %0;" : "+l"(d) : "l"(a), "l"(b));
}
__device__ __forceinline__ unsigned long long addf2(unsigned long long a,
                                                    unsigned long long b) {
    unsigned long long r;
    asm("add.rn.f32x2 %0, %1, %2;" : "=l"(r) : "l"(a), "l"(b));
    return r;
}

// ===========================================================================
// K1: phases A (LN stats + k/v proj + masked qsum) and C (softmax, o)
// ===========================================================================
__global__ void __launch_bounds__(NTHR1, 1)
msa_k1(const float* __restrict__ m,    const float* __restrict__ mask,
       const float* __restrict__ ln_w, const float* __restrict__ ln_b,
       const float* __restrict__ wq,   const float* __restrict__ wk,
       const float* __restrict__ wv)
{
    extern __shared__ float smf[];
    unsigned long long* kbuf_u = reinterpret_cast<unsigned long long*>(smf);
    unsigned long long* vbuf_u = kbuf_u + 4 * S_DIM;
    float* wk_s  = smf + OFF_WK;
    float* wv_s  = smf + OFF_WV;
    float* qvec_s= smf + OFF_QVEC;
    float* qh_s  = smf + OFF_QH;
    float* red   = smf + OFF_RED;
    float* max_sh= smf + OFF_MAX;
    // ln params staged in red area head before use? keep registers via __ldg
    __shared__ float lnw_s[64], lnb_s[64];

    const int tid  = threadIdx.x;
    const int r    = blockIdx.x;
    const int lane = tid & 31;
    const int wid  = tid >> 5;

    for (int i = tid; i < 512; i += NTHR1) { wk_s[i] = wk[i]; wv_s[i] = wv[i]; }
    if (tid < 64) { lnw_s[tid] = ln_w[tid]; lnb_s[tid] = ln_b[tid]; }
    __syncthreads();

    // ---------------- Phase A ----------------
    unsigned long long qsum2[32];
    #pragma unroll
    for (int t = 0; t < 32; ++t) qsum2[t] = 0ull;
    float msum = 0.f;

    #pragma unroll 1
    for (int i = 0; i < RPT; ++i) {
        const int s = tid + NTHR1 * i;
        const float4* xr = reinterpret_cast<const float4*>(m + ((size_t)s * R_DIM + r) * CE);
        float sum = 0.f, sq = 0.f;
        #pragma unroll
        for (int t = 0; t < 16; ++t) {
            float4 v = __ldg(xr + t);
            sum += v.x + v.y + v.z + v.w;
            sq = fmaf(v.x, v.x, sq); sq = fmaf(v.y, v.y, sq);
            sq = fmaf(v.z, v.z, sq); sq = fmaf(v.w, v.w, sq);
        }
        const float muv  = sum * (1.f / CE);
        const float var  = sq * (1.f / CE) - muv * muv;
        const float rstd = rsqrtf(var + 1e-5f);
        const float mk   = __ldg(mask + (size_t)s * R_DIM + r);
        g_stat[(size_t)r * S_DIM + s] = make_float2(muv, rstd);
        msum += mk;
        const unsigned long long mk2 = pack2(mk);

        unsigned long long ka[4], va[4];
        #pragma unroll
        for (int t = 0; t < 4; ++t) { ka[t] = 0ull; va[t] = 0ull; }

        #pragma unroll
        for (int t = 0; t < 16; ++t) {
            float4 v  = __ldg(xr + t);
            float4 lw = reinterpret_cast<const float4*>(lnw_s)[t];
            float4 lb = reinterpret_cast<const float4*>(lnb_s)[t];
            float xn0 = (v.x - muv) * rstd * lw.x + lb.x;
            float xn1 = (v.y - muv) * rstd * lw.y + lb.y;
            float xn2 = (v.z - muv) * rstd * lw.z + lb.z;
            float xn3 = (v.w - muv) * rstd * lw.w + lb.w;
            ffma2(qsum2[2*t],   packAB(xn0, xn1), mk2);
            ffma2(qsum2[2*t+1], packAB(xn2, xn3), mk2);
            const float xnv[4] = {xn0, xn1, xn2, xn3};
            #pragma unroll
            for (int j = 0; j < 4; ++j) {
                const int c = 4*t + j;
                const unsigned long long xx = pack2(xnv[j]);
                u64x2 k0 = reinterpret_cast<const u64x2*>(wk_s + c * 8)[0];
                u64x2 v0 = reinterpret_cast<const u64x2*>(wv_s + c * 8)[0];
                u64x2 k1 = reinterpret_cast<const u64x2*>(wk_s + c * 8)[1];
                u64x2 v1 = reinterpret_cast<const u64x2*>(wv_s + c * 8)[1];
                ffma2(ka[0], xx, k0.a); ffma2(ka[1], xx, k0.b);
                ffma2(ka[2], xx, k1.a); ffma2(ka[3], xx, k1.b);
                ffma2(va[0], xx, v0.a); ffma2(va[1], xx, v0.b);
                ffma2(va[2], xx, v1.a); ffma2(va[3], xx, v1.b);
            }
        }
        #pragma unroll
        for (int t = 0; t < 4; ++t) {
            kbuf_u[t * S_DIM + s] = ka[t];
            vbuf_u[t * S_DIM + s] = va[t];
        }
    }

    #pragma unroll
    for (int t = 0; t < 32; ++t) {
        #pragma unroll
        for (int o = 16; o > 0; o >>= 1)
            qsum2[t] = addf2(qsum2[t], __shfl_xor_sync(0xffffffffu, qsum2[t], o));
    }
    #pragma unroll
    for (int o = 16; o > 0; o >>= 1)
        msum += __shfl_xor_sync(0xffffffffu, msum, o);
    if (lane == 0) {
        #pragma unroll
        for (int t = 0; t < 32; ++t) {
            float2 p = unpack2(qsum2[t]);
            red[wid * 72 + 2*t] = p.x; red[wid * 72 + 2*t+1] = p.y;
        }
        red[wid * 72 + 64] = msum;
    }
    __syncthreads();

    if (tid < 64) {
        float t0 = 0.f, ms = 0.f;
        #pragma unroll
        for (int w = 0; w < 16; ++w) { t0 += red[w * 72 + tid]; ms += red[w * 72 + 64]; }
        qvec_s[tid] = t0 * __fdividef(1.f, ms + 1e-10f);
    }
    __syncthreads();
    if (tid < 64) {
        float acc = 0.f;
        #pragma unroll 8
        for (int c = 0; c < CE; ++c) acc = fmaf(qvec_s[c], __ldg(wq + c * 64 + tid), acc);
        qh_s[tid] = acc * 0.3535533905932738f;
    }
    __syncthreads();

    // ---------------- Phase C ----------------
    float sc[RPT][8], mh[8];
    #pragma unroll
    for (int h = 0; h < 8; ++h) mh[h] = -1e30f;

    #pragma unroll
    for (int i = 0; i < RPT; ++i) {
        const int s = tid + NTHR1 * i;
        unsigned long long kk[4];
        #pragma unroll
        for (int j = 0; j < 4; ++j) kk[j] = kbuf_u[j * S_DIM + s];
        const float bias = 1e9f * (__ldg(mask + (size_t)s * R_DIM + r) - 1.f);
        #pragma unroll
        for (int h = 0; h < 8; ++h) {
            unsigned long long acc = 0ull;
            #pragma unroll
            for (int j = 0; j < 4; ++j) {
                unsigned long long q2 =
                    reinterpret_cast<const unsigned long long*>(qh_s)[h*4+j];
                ffma2(acc, q2, kk[j]);
            }
            float2 p = unpack2(acc);
            float a = bias + p.x + p.y;
            sc[i][h] = a;
            mh[h] = fmaxf(mh[h], a);
        }
    }
    #pragma unroll
    for (int h = 0; h < 8; ++h) {
        #pragma unroll
        for (int o = 16; o > 0; o >>= 1)
            mh[h] = fmaxf(mh[h], __shfl_xor_sync(0xffffffffu, mh[h], o));
    }
    if (lane == 0) {
        #pragma unroll
        for (int h = 0; h < 8; ++h) red[wid * 72 + h] = mh[h];
    }
    __syncthreads();
    if (tid < 8) {
        float mm = -1e30f;
        #pragma unroll
        for (int w = 0; w < 16; ++w) mm = fmaxf(mm, red[w * 72 + tid]);
        max_sh[tid] = mm;
    }
    __syncthreads();

    #pragma unroll 1
    for (int hb = 0; hb < 2; ++hb) {
        unsigned long long oacc2[16];
        float sumh[4];
        #pragma unroll
        for (int t = 0; t < 16; ++t) oacc2[t] = 0ull;
        #pragma unroll
        for (int h = 0; h < 4; ++h) sumh[h] = 0.f;

        #pragma unroll
        for (int i = 0; i < RPT; ++i) {
            const int s = tid + NTHR1 * i;
            unsigned long long vv[4];
            #pragma unroll
            for (int j = 0; j < 4; ++j) vv[j] = vbuf_u[j * S_DIM + s];
            #pragma unroll
            for (int h = 0; h < 4; ++h) {
                const int hh = hb * 4 + h;
                const float e = __expf(sc[i][hh] - max_sh[hh]);
                sumh[h] += e;
                const unsigned long long e2 = pack2(e);
                #pragma unroll
                for (int j = 0; j < 4; ++j) ffma2(oacc2[h*4+j], e2, vv[j]);
            }
        }
        #pragma unroll
        for (int t = 0; t < 16; ++t) {
            #pragma unroll
            for (int o = 16; o > 0; o >>= 1)
                oacc2[t] = addf2(oacc2[t], __shfl_xor_sync(0xffffffffu, oacc2[t], o));
        }
        #pragma unroll
        for (int h = 0; h < 4; ++h) {
            #pragma unroll
            for (int o = 16; o > 0; o >>= 1)
                sumh[h] += __shfl_xor_sync(0xffffffffu, sumh[h], o);
        }
        if (lane == 0) {
            #pragma unroll
            for (int t = 0; t < 16; ++t) {
                float2 p = unpack2(oacc2[t]);
                red[wid * 72 + hb*32 + 2*t]   = p.x;
                red[wid * 72 + hb*32 + 2*t+1] = p.y;
            }
            #pragma unroll
            for (int h = 0; h < 4; ++h) red[wid * 72 + 64 + hb*4 + h] = sumh[h];
        }
        __syncthreads();
    }
    if (tid < 64) {
        float t0 = 0.f, ss = 0.f;
        #pragma unroll
        for (int w = 0; w < 16; ++w) {
            t0 += red[w * 72 + tid];
            ss += red[w * 72 + 64 + (tid >> 3)];
        }
        g_osh[r * CE + tid] = __fdividef(t0, ss);
    }
}

// ===========================================================================
// K2: phase D — gate GEMM + output GEMM, 1024 threads, 8 warps/SMSP
// ===========================================================================
__device__ __forceinline__ void gemm64_512(const float* __restrict__ xb_base,
                                           const unsigned long long* __restrict__ wtab,
                                           const unsigned long long* __restrict__ bias,
                                           int R0, int cg,
                                           unsigned long long acc[2][8])
{
    #pragma unroll
    for (int j = 0; j < 2; ++j)
        #pragma unroll
        for (int cc = 0; cc < 8; ++cc) acc[j][cc] = bias[cg * 8 + cc];

    #pragma unroll 2
    for (int c4 = 0; c4 < 16; ++c4) {
        const int sw = 2 * c4;
        const int i0 = R0 ^ sw;
        const int i1 = i0 ^ 2;
        const float* xb = xb_base + c4 * 4 * 512;
        const unsigned long long* wr = wtab + c4 * 4 * WD + cg * 10;
        #pragma unroll
        for (int ci = 0; ci < 4; ++ci) {
            unsigned long long x0 =
                *reinterpret_cast<const unsigned long long*>(xb + ci * 512 + i0);
            unsigned long long x1 =
                *reinterpret_cast<const unsigned long long*>(xb + ci * 512 + i1);
            const u64x2* wp = reinterpret_cast<const u64x2*>(wr + ci * WD);
            u64x2 w0 = wp[0], w1 = wp[1], w2 = wp[2], w3 = wp[3];
            ffma2(acc[0][0], x0, w0.a); ffma2(acc[0][1], x0, w0.b);
            ffma2(acc[0][2], x0, w1.a); ffma2(acc[0][3], x0, w1.b);
            ffma2(acc[0][4], x0, w2.a); ffma2(acc[0][5], x0, w2.b);
            ffma2(acc[0][6], x0, w3.a); ffma2(acc[0][7], x0, w3.b);
            ffma2(acc[1][0], x1, w0.a); ffma2(acc[1][1], x1, w0.b);
            ffma2(acc[1][2], x1, w1.a); ffma2(acc[1][3], x1, w1.b);
            ffma2(acc[1][4], x1, w2.a); ffma2(acc[1][5], x1, w2.b);
            ffma2(acc[1][6], x1, w3.a); ffma2(acc[1][7], x1, w3.b);
        }
    }
}

__global__ void __launch_bounds__(NTHR2, 1)
msa_k2(const float* __restrict__ m,    const float* __restrict__ ln_w,
       const float* __restrict__ ln_b, const float* __restrict__ wg,
       const float* __restrict__ bg,   const float* __restrict__ wo,
       const float* __restrict__ bo,   float* __restrict__ out)
{
    extern __shared__ float smf[];
    unsigned long long* wg_u = reinterpret_cast<unsigned long long*>(smf);
    unsigned long long* wo_u = wg_u + 64 * WD;
    float* xnT   = smf + K2_XNT;
    float* lnw_s = smf + K2_LNW;
    float* lnb_s = smf + K2_LNB;
    unsigned long long* bgd = reinterpret_cast<unsigned long long*>(smf + K2_BGD);
    unsigned long long* bod = reinterpret_cast<unsigned long long*>(smf + K2_BOD);
    float* osh_s = smf + K2_OSH;

    const int tid = threadIdx.x;
    const int r   = blockIdx.x;

    // dup-pair weight tables
    for (int idx = tid; idx < 4096; idx += NTHR2) {
        const int c = idx >> 6, col = idx & 63;
        const int dst = c * WD + (col >> 3) * 10 + (col & 7);
        wg_u[dst] = pack2(__ldg(wg + idx));
        wo_u[dst] = pack2(__ldg(wo + idx));
    }
    if (tid < 64) {
        lnw_s[tid] = __ldg(ln_w + tid);
        lnb_s[tid] = __ldg(ln_b + tid);
        bgd[tid] = pack2(__ldg(bg + tid));
        bod[tid] = pack2(__ldg(bo + tid));
        osh_s[tid] = g_osh[r * CE + tid];
    }
    __syncthreads();

    const int cg  = tid & 7;
    const int rg  = tid >> 3;
    const int R0  = rg * 4;          // 4 rows per thread, 512-row chunk
    const int c4l = tid & 15;        // loader column-quad
    const int rw0 = tid >> 4;        // loader base row (0..63)
    const float4 lwv = reinterpret_cast<const float4*>(lnw_s)[c4l];
    const float4 lbv = reinterpret_cast<const float4*>(lnb_s)[c4l];

    #pragma unroll 1
    for (int ch = 0; ch < NCH; ++ch) {
        const int S0 = ch * CHUNK;

        // ---- load + normalize chunk into swizzled xnT ----
        #pragma unroll
        for (int k = 0; k < 8; ++k) {
            const int row = rw0 + 64 * k;
            float2 st = __ldg(&g_stat[(size_t)r * S_DIM + S0 + row]);
            float4 v  = __ldg(reinterpret_cast<const float4*>(
                          m + ((size_t)(S0 + row) * R_DIM + r) * CE) + c4l);
            const int rw = row ^ (2 * c4l);
            xnT[(4*c4l+0) * 512 + rw] = (v.x - st.x) * st.y * lwv.x + lbv.x;
            xnT[(4*c4l+1) * 512 + rw] = (v.y - st.x) * st.y * lwv.y + lbv.y;
            xnT[(4*c4l+2) * 512 + rw] = (v.z - st.x) * st.y * lwv.z + lbv.z;
            xnT[(4*c4l+3) * 512 + rw] = (v.w - st.x) * st.y * lwv.w + lbv.w;
        }
        __syncthreads();

        // ---- GEMM1: gate = xn @ wg + bg ----
        unsigned long long acc[2][8];
        gemm64_512(xnT, wg_u, bgd, R0, cg, acc);
        __syncthreads();

        // ---- sigmoid * o -> gg, overwrite xnT (transposed, same swizzle) ----
        #pragma unroll
        for (int cc = 0; cc < 8; ++cc) {
            const int col = cg * 8 + cc;
            const float osv = osh_s[col];
            float* gb = xnT + col * 512;
            const int sw = (col >> 2) << 1;
            const int i0 = R0 ^ sw;
            #pragma unroll
            for (int j = 0; j < 2; ++j) {
                float2 p2 = unpack2(acc[j][cc]);
                const float g0 = osv * __fdividef(1.f, 1.f + __expf(-p2.x));
                const float g1 = osv * __fdividef(1.f, 1.f + __expf(-p2.y));
                *reinterpret_cast<unsigned long long*>(gb + (j ? (i0 ^ 2) : i0)) =
                    packAB(g0, g1);
            }
        }
        __syncthreads();

        // ---- GEMM2: out = gg @ wo + bo ----
        unsigned long long acc2[2][8];
        gemm64_512(xnT, wo_u, bod, R0, cg, acc2);

        #pragma unroll
        for (int j = 0; j < 2; ++j) {
            float lo[8], hi[8];
            #pragma unroll
            for (int cc = 0; cc < 8; ++cc) {
                float2 p2 = unpack2(acc2[j][cc]);
                lo[cc] = p2.x; hi[cc] = p2.y;
            }
            const int s0 = S0 + R0 + 2*j;
            float* o0 = out + ((size_t)s0 * R_DIM + r) * CE + cg * 8;
            float* o1 = o0 + (size_t)R_DIM * CE;
            reinterpret_cast<float4*>(o0)[0] = make_float4(lo[0], lo[1], lo[2], lo[3]);
            reinterpret_cast<float4*>(o0)[1] = make_float4(lo[4], lo[5], lo[6], lo[7]);
            reinterpret_cast<float4*>(o1)[0] = make_float4(hi[0], hi[1], hi[2], hi[3]);
            reinterpret_cast<float4*>(o1)[1] = make_float4(hi[4], hi[5], hi[6], hi[7]);
        }
        __syncthreads();
    }
}

extern "C" void kernel_launch(void* const* d_in, const int* in_sizes, int n_in,
                              void* d_out, int out_size)
{
    (void)in_sizes; (void)n_in; (void)out_size;
    const float* m    = (const float*)d_in[0];
    const float* mask = (const float*)d_in[1];
    const float* ln_w = (const float*)d_in[2];
    const float* ln_b = (const float*)d_in[3];
    const float* wq   = (const float*)d_in[4];
    const float* wk   = (const float*)d_in[5];
    const float* wv   = (const float*)d_in[6];
    const float* wg   = (const float*)d_in[7];
    const float* bg   = (const float*)d_in[8];
    const float* wo   = (const float*)d_in[9];
    const float* bo   = (const float*)d_in[10];
    float* out = (float*)d_out;

    cudaFuncSetAttribute(msa_k1,
                         cudaFuncAttributeMaxDynamicSharedMemorySize, (int)SMEM1_BYTES);
    cudaFuncSetAttribute(msa_k2,
                         cudaFuncAttributeMaxDynamicSharedMemorySize, (int)SMEM2_BYTES);

    msa_k1<<<R_DIM, NTHR1, SMEM1_BYTES>>>(m, mask, ln_w, ln_b, wq, wk, wv);
    msa_k2<<<R_DIM, NTHR2, SMEM2_BYTES>>>(m, ln_w, ln_b, wg, bg, wo, bo, out);
}

// round 6
// speedup vs baseline: 1.1554x; 1.1446x over previous
#include <cuda_runtime.h>
#include <cstdint>
#include <cstddef>

namespace {
constexpr int S_DIM = 2048, R_DIM = 384, CE = 64;
// ---- K1 (phases A+C): 512 threads ----
constexpr int NTHR1 = 512, RPT = 4;
constexpr int OFF_WK = 33024, OFF_WV = 33536, OFF_QVEC = 34048, OFF_QH = 34112;
constexpr int OFF_RED = 34176, OFF_MAX = 35328;
constexpr int SMEM1_FL = 35344;
constexpr size_t SMEM1_BYTES = (size_t)SMEM1_FL * 4;
// ---- K2 (phase D): 512 threads, 8x8 register tile ----
constexpr int NTHR2 = 512, CHUNK = 512, NCH = 4;
constexpr int WD = 80;                      // u64 per dup-weight row
constexpr int K2_XNT = 20480;               // fl offset of xnT[64][512]
constexpr int K2_LNW = 53248, K2_LNB = 53312, K2_BGD = 53376, K2_BOD = 53504;
constexpr int K2_OSH = 53632;
constexpr int SMEM2_FL = 53696;
constexpr size_t SMEM2_BYTES = (size_t)SMEM2_FL * 4;
}

__device__ float2 g_stat[(size_t)R_DIM * S_DIM];   // (mu, rstd) per (r, s)
__device__ float  g_osh[(size_t)R_DIM * CE];       // o_flat per column

struct alignas(16) u64x2 { unsigned long long a, b; };

__device__ __forceinline__ unsigned long long pack2(float x) {
    unsigned long long r;
    asm("mov.b64 %0, {%1, %2};" : "=l"(r) : "f"(x), "f"(x));
    return r;
}
__device__ __forceinline__ unsigned long long packAB(float a, float b) {
    unsigned long long r;
    asm("mov.b64 %0, {%1, %2};" : "=l"(r) : "f"(a), "f"(b));
    return r;
}
__device__ __forceinline__ float2 unpack2(unsigned long long v) {
    float2 f;
    asm("mov.b64 {%0, %1}, %2;" : "=f"(f.x), "=f"(f.y) : "l"(v));
    return f;
}
__device__ __forceinline__ void ffma2(unsigned long long& d,
                                      unsigned long long a, unsigned long long b) {
    asm("fma.rn.f32x2 %0, %1, %2, %0;" : "+l"(d) : "l"(a), "l"(b));
}
__device__ __forceinline__ unsigned long long addf2(unsigned long long a,
                                                    unsigned long long b) {
    unsigned long long r;
    asm("add.rn.f32x2 %0, %1, %2;" : "=l"(r) : "l"(a), "l"(b));
    return r;
}

// ===========================================================================
// K1: phases A (LN stats + k/v proj + masked qsum) and C (softmax, o)
// ===========================================================================
__global__ void __launch_bounds__(NTHR1, 1)
msa_k1(const float* __restrict__ m,    const float* __restrict__ mask,
       const float* __restrict__ ln_w, const float* __restrict__ ln_b,
       const float* __restrict__ wq,   const float* __restrict__ wk,
       const float* __restrict__ wv)
{
    extern __shared__ float smf[];
    unsigned long long* kbuf_u = reinterpret_cast<unsigned long long*>(smf);
    unsigned long long* vbuf_u = kbuf_u + 4 * S_DIM;
    float* wk_s  = smf + OFF_WK;
    float* wv_s  = smf + OFF_WV;
    float* qvec_s= smf + OFF_QVEC;
    float* qh_s  = smf + OFF_QH;
    float* red   = smf + OFF_RED;
    float* max_sh= smf + OFF_MAX;
    __shared__ float lnw_s[64], lnb_s[64];

    const int tid  = threadIdx.x;
    const int r    = blockIdx.x;
    const int lane = tid & 31;
    const int wid  = tid >> 5;

    for (int i = tid; i < 512; i += NTHR1) { wk_s[i] = wk[i]; wv_s[i] = wv[i]; }
    if (tid < 64) { lnw_s[tid] = ln_w[tid]; lnb_s[tid] = ln_b[tid]; }
    __syncthreads();

    // ---------------- Phase A ----------------
    unsigned long long qsum2[32];
    #pragma unroll
    for (int t = 0; t < 32; ++t) qsum2[t] = 0ull;
    float msum = 0.f;

    #pragma unroll 1
    for (int i = 0; i < RPT; ++i) {
        const int s = tid + NTHR1 * i;
        const float4* xr = reinterpret_cast<const float4*>(m + ((size_t)s * R_DIM + r) * CE);
        float sum = 0.f, sq = 0.f;
        #pragma unroll
        for (int t = 0; t < 16; ++t) {
            float4 v = __ldg(xr + t);
            sum += v.x + v.y + v.z + v.w;
            sq = fmaf(v.x, v.x, sq); sq = fmaf(v.y, v.y, sq);
            sq = fmaf(v.z, v.z, sq); sq = fmaf(v.w, v.w, sq);
        }
        const float muv  = sum * (1.f / CE);
        const float var  = sq * (1.f / CE) - muv * muv;
        const float rstd = rsqrtf(var + 1e-5f);
        const float mk   = __ldg(mask + (size_t)s * R_DIM + r);
        g_stat[(size_t)r * S_DIM + s] = make_float2(muv, rstd);
        msum += mk;
        const unsigned long long mk2 = pack2(mk);

        unsigned long long ka[4], va[4];
        #pragma unroll
        for (int t = 0; t < 4; ++t) { ka[t] = 0ull; va[t] = 0ull; }

        #pragma unroll
        for (int t = 0; t < 16; ++t) {
            float4 v  = __ldg(xr + t);
            float4 lw = reinterpret_cast<const float4*>(lnw_s)[t];
            float4 lb = reinterpret_cast<const float4*>(lnb_s)[t];
            float xn0 = (v.x - muv) * rstd * lw.x + lb.x;
            float xn1 = (v.y - muv) * rstd * lw.y + lb.y;
            float xn2 = (v.z - muv) * rstd * lw.z + lb.z;
            float xn3 = (v.w - muv) * rstd * lw.w + lb.w;
            ffma2(qsum2[2*t],   packAB(xn0, xn1), mk2);
            ffma2(qsum2[2*t+1], packAB(xn2, xn3), mk2);
            const float xnv[4] = {xn0, xn1, xn2, xn3};
            #pragma unroll
            for (int j = 0; j < 4; ++j) {
                const int c = 4*t + j;
                const unsigned long long xx = pack2(xnv[j]);
                u64x2 k0 = reinterpret_cast<const u64x2*>(wk_s + c * 8)[0];
                u64x2 v0 = reinterpret_cast<const u64x2*>(wv_s + c * 8)[0];
                u64x2 k1 = reinterpret_cast<const u64x2*>(wk_s + c * 8)[1];
                u64x2 v1 = reinterpret_cast<const u64x2*>(wv_s + c * 8)[1];
                ffma2(ka[0], xx, k0.a); ffma2(ka[1], xx, k0.b);
                ffma2(ka[2], xx, k1.a); ffma2(ka[3], xx, k1.b);
                ffma2(va[0], xx, v0.a); ffma2(va[1], xx, v0.b);
                ffma2(va[2], xx, v1.a); ffma2(va[3], xx, v1.b);
            }
        }
        #pragma unroll
        for (int t = 0; t < 4; ++t) {
            kbuf_u[t * S_DIM + s] = ka[t];
            vbuf_u[t * S_DIM + s] = va[t];
        }
    }

    #pragma unroll
    for (int t = 0; t < 32; ++t) {
        #pragma unroll
        for (int o = 16; o > 0; o >>= 1)
            qsum2[t] = addf2(qsum2[t], __shfl_xor_sync(0xffffffffu, qsum2[t], o));
    }
    #pragma unroll
    for (int o = 16; o > 0; o >>= 1)
        msum += __shfl_xor_sync(0xffffffffu, msum, o);
    if (lane == 0) {
        #pragma unroll
        for (int t = 0; t < 32; ++t) {
            float2 p = unpack2(qsum2[t]);
            red[wid * 72 + 2*t] = p.x; red[wid * 72 + 2*t+1] = p.y;
        }
        red[wid * 72 + 64] = msum;
    }
    __syncthreads();

    if (tid < 64) {
        float t0 = 0.f, ms = 0.f;
        #pragma unroll
        for (int w = 0; w < 16; ++w) { t0 += red[w * 72 + tid]; ms += red[w * 72 + 64]; }
        qvec_s[tid] = t0 * __fdividef(1.f, ms + 1e-10f);
    }
    __syncthreads();
    if (tid < 64) {
        float acc = 0.f;
        #pragma unroll 8
        for (int c = 0; c < CE; ++c) acc = fmaf(qvec_s[c], __ldg(wq + c * 64 + tid), acc);
        qh_s[tid] = acc * 0.3535533905932738f;
    }
    __syncthreads();

    // ---------------- Phase C ----------------
    float sc[RPT][8], mh[8];
    #pragma unroll
    for (int h = 0; h < 8; ++h) mh[h] = -1e30f;

    #pragma unroll
    for (int i = 0; i < RPT; ++i) {
        const int s = tid + NTHR1 * i;
        unsigned long long kk[4];
        #pragma unroll
        for (int j = 0; j < 4; ++j) kk[j] = kbuf_u[j * S_DIM + s];
        const float bias = 1e9f * (__ldg(mask + (size_t)s * R_DIM + r) - 1.f);
        #pragma unroll
        for (int h = 0; h < 8; ++h) {
            unsigned long long acc = 0ull;
            #pragma unroll
            for (int j = 0; j < 4; ++j) {
                unsigned long long q2 =
                    reinterpret_cast<const unsigned long long*>(qh_s)[h*4+j];
                ffma2(acc, q2, kk[j]);
            }
            float2 p = unpack2(acc);
            float a = bias + p.x + p.y;
            sc[i][h] = a;
            mh[h] = fmaxf(mh[h], a);
        }
    }
    #pragma unroll
    for (int h = 0; h < 8; ++h) {
        #pragma unroll
        for (int o = 16; o > 0; o >>= 1)
            mh[h] = fmaxf(mh[h], __shfl_xor_sync(0xffffffffu, mh[h], o));
    }
    if (lane == 0) {
        #pragma unroll
        for (int h = 0; h < 8; ++h) red[wid * 72 + h] = mh[h];
    }
    __syncthreads();
    if (tid < 8) {
        float mm = -1e30f;
        #pragma unroll
        for (int w = 0; w < 16; ++w) mm = fmaxf(mm, red[w * 72 + tid]);
        max_sh[tid] = mm;
    }
    __syncthreads();

    #pragma unroll 1
    for (int hb = 0; hb < 2; ++hb) {
        unsigned long long oacc2[16];
        float sumh[4];
        #pragma unroll
        for (int t = 0; t < 16; ++t) oacc2[t] = 0ull;
        #pragma unroll
        for (int h = 0; h < 4; ++h) sumh[h] = 0.f;

        #pragma unroll
        for (int i = 0; i < RPT; ++i) {
            const int s = tid + NTHR1 * i;
            unsigned long long vv[4];
            #pragma unroll
            for (int j = 0; j < 4; ++j) vv[j] = vbuf_u[j * S_DIM + s];
            #pragma unroll
            for (int h = 0; h < 4; ++h) {
                const int hh = hb * 4 + h;
                const float e = __expf(sc[i][hh] - max_sh[hh]);
                sumh[h] += e;
                const unsigned long long e2 = pack2(e);
                #pragma unroll
                for (int j = 0; j < 4; ++j) ffma2(oacc2[h*4+j], e2, vv[j]);
            }
        }
        #pragma unroll
        for (int t = 0; t < 16; ++t) {
            #pragma unroll
            for (int o = 16; o > 0; o >>= 1)
                oacc2[t] = addf2(oacc2[t], __shfl_xor_sync(0xffffffffu, oacc2[t], o));
        }
        #pragma unroll
        for (int h = 0; h < 4; ++h) {
            #pragma unroll
            for (int o = 16; o > 0; o >>= 1)
                sumh[h] += __shfl_xor_sync(0xffffffffu, sumh[h], o);
        }
        if (lane == 0) {
            #pragma unroll
            for (int t = 0; t < 16; ++t) {
                float2 p = unpack2(oacc2[t]);
                red[wid * 72 + hb*32 + 2*t]   = p.x;
                red[wid * 72 + hb*32 + 2*t+1] = p.y;
            }
            #pragma unroll
            for (int h = 0; h < 4; ++h) red[wid * 72 + 64 + hb*4 + h] = sumh[h];
        }
        __syncthreads();
    }
    if (tid < 64) {
        float t0 = 0.f, ss = 0.f;
        #pragma unroll
        for (int w = 0; w < 16; ++w) {
            t0 += red[w * 72 + tid];
            ss += red[w * 72 + 64 + (tid >> 3)];
        }
        g_osh[r * CE + tid] = __fdividef(t0, ss);
    }
}

// ===========================================================================
// K2: phase D — 512 threads, 8-row x 8-col register tile, all-LDS.128 GEMM
// ===========================================================================
__device__ __forceinline__ void gemm64_8r(const float* __restrict__ xb_base,
                                          const unsigned long long* __restrict__ wtab,
                                          const unsigned long long* __restrict__ bias,
                                          int R0, int cg,
                                          unsigned long long acc[4][8])
{
    #pragma unroll
    for (int k = 0; k < 4; ++k)
        #pragma unroll
        for (int cc = 0; cc < 8; ++cc) acc[k][cc] = bias[cg * 8 + cc];

    #pragma unroll 2
    for (int c4 = 0; c4 < 16; ++c4) {
        const int p = c4 & 3;                       // compile-time u64 permute
        const int base = (R0 ^ (2 * c4)) & ~7;      // aligned 8-float block
        const float* xcol = xb_base + c4 * 4 * 512 + base;
        const unsigned long long* wr = wtab + c4 * 4 * WD + cg * 10;
        #pragma unroll
        for (int ci = 0; ci < 4; ++ci) {
            u64x2 ua = *reinterpret_cast<const u64x2*>(xcol + ci * 512);
            u64x2 ub = *reinterpret_cast<const u64x2*>(xcol + ci * 512 + 4);
            // row-pair k lives at u64 index k ^ p within {ua.a, ua.b, ub.a, ub.b}
            unsigned long long u0 = ua.a, u1 = ua.b, u2 = ub.a, u3 = ub.b;
            unsigned long long x0 = (p == 0) ? u0 : (p == 1) ? u1 : (p == 2) ? u2 : u3;
            unsigned long long x1 = (p == 0) ? u1 : (p == 1) ? u0 : (p == 2) ? u3 : u2;
            unsigned long long x2 = (p == 0) ? u2 : (p == 1) ? u3 : (p == 2) ? u0 : u1;
            unsigned long long x3 = (p == 0) ? u3 : (p == 1) ? u2 : (p == 2) ? u1 : u0;
            const u64x2* wp = reinterpret_cast<const u64x2*>(wr + ci * WD);
            u64x2 w0 = wp[0], w1 = wp[1], w2 = wp[2], w3 = wp[3];
            ffma2(acc[0][0], x0, w0.a); ffma2(acc[0][1], x0, w0.b);
            ffma2(acc[0][2], x0, w1.a); ffma2(acc[0][3], x0, w1.b);
            ffma2(acc[0][4], x0, w2.a); ffma2(acc[0][5], x0, w2.b);
            ffma2(acc[0][6], x0, w3.a); ffma2(acc[0][7], x0, w3.b);
            ffma2(acc[1][0], x1, w0.a); ffma2(acc[1][1], x1, w0.b);
            ffma2(acc[1][2], x1, w1.a); ffma2(acc[1][3], x1, w1.b);
            ffma2(acc[1][4], x1, w2.a); ffma2(acc[1][5], x1, w2.b);
            ffma2(acc[1][6], x1, w3.a); ffma2(acc[1][7], x1, w3.b);
            ffma2(acc[2][0], x2, w0.a); ffma2(acc[2][1], x2, w0.b);
            ffma2(acc[2][2], x2, w1.a); ffma2(acc[2][3], x2, w1.b);
            ffma2(acc[2][4], x2, w2.a); ffma2(acc[2][5], x2, w2.b);
            ffma2(acc[2][6], x2, w3.a); ffma2(acc[2][7], x2, w3.b);
            ffma2(acc[3][0], x3, w0.a); ffma2(acc[3][1], x3, w0.b);
            ffma2(acc[3][2], x3, w1.a); ffma2(acc[3][3], x3, w1.b);
            ffma2(acc[3][4], x3, w2.a); ffma2(acc[3][5], x3, w2.b);
            ffma2(acc[3][6], x3, w3.a); ffma2(acc[3][7], x3, w3.b);
        }
    }
}

__global__ void __launch_bounds__(NTHR2, 1)
msa_k2(const float* __restrict__ m,    const float* __restrict__ ln_w,
       const float* __restrict__ ln_b, const float* __restrict__ wg,
       const float* __restrict__ bg,   const float* __restrict__ wo,
       const float* __restrict__ bo,   float* __restrict__ out)
{
    extern __shared__ float smf[];
    unsigned long long* wg_u = reinterpret_cast<unsigned long long*>(smf);
    unsigned long long* wo_u = wg_u + 64 * WD;
    float* xnT   = smf + K2_XNT;
    float* lnw_s = smf + K2_LNW;
    float* lnb_s = smf + K2_LNB;
    unsigned long long* bgd = reinterpret_cast<unsigned long long*>(smf + K2_BGD);
    unsigned long long* bod = reinterpret_cast<unsigned long long*>(smf + K2_BOD);
    float* osh_s = smf + K2_OSH;

    const int tid = threadIdx.x;
    const int r   = blockIdx.x;

    // dup-pair weight tables: row c, 8 groups of (8 data + 2 pad) u64
    for (int idx = tid; idx < 4096; idx += NTHR2) {
        const int c = idx >> 6, col = idx & 63;
        const int dst = c * WD + (col >> 3) * 10 + (col & 7);
        wg_u[dst] = pack2(__ldg(wg + idx));
        wo_u[dst] = pack2(__ldg(wo + idx));
    }
    if (tid < 64) {
        lnw_s[tid] = __ldg(ln_w + tid);
        lnb_s[tid] = __ldg(ln_b + tid);
        bgd[tid] = pack2(__ldg(bg + tid));
        bod[tid] = pack2(__ldg(bo + tid));
        osh_s[tid] = g_osh[r * CE + tid];
    }
    __syncthreads();

    const int cg  = tid & 7;
    const int rg  = tid >> 3;        // 0..63
    const int R0  = rg * 8;          // 8 rows per thread, 512-row chunk
    const int c4l = tid & 15;        // loader column-quad
    const int rw0 = tid >> 4;        // loader base row (0..31)
    const float4 lwv = reinterpret_cast<const float4*>(lnw_s)[c4l];
    const float4 lbv = reinterpret_cast<const float4*>(lnb_s)[c4l];

    #pragma unroll 1
    for (int ch = 0; ch < NCH; ++ch) {
        const int S0 = ch * CHUNK;

        // ---- load + normalize chunk into swizzled xnT ----
        #pragma unroll
        for (int k = 0; k < 16; ++k) {
            const int row = rw0 + 32 * k;
            float2 st = __ldg(&g_stat[(size_t)r * S_DIM + S0 + row]);
            float4 v  = __ldg(reinterpret_cast<const float4*>(
                          m + ((size_t)(S0 + row) * R_DIM + r) * CE) + c4l);
            const int rw = row ^ (2 * c4l);
            xnT[(4*c4l+0) * 512 + rw] = (v.x - st.x) * st.y * lwv.x + lbv.x;
            xnT[(4*c4l+1) * 512 + rw] = (v.y - st.x) * st.y * lwv.y + lbv.y;
            xnT[(4*c4l+2) * 512 + rw] = (v.z - st.x) * st.y * lwv.z + lbv.z;
            xnT[(4*c4l+3) * 512 + rw] = (v.w - st.x) * st.y * lwv.w + lbv.w;
        }
        __syncthreads();

        // ---- GEMM1: gate = xn @ wg + bg ----
        unsigned long long acc[4][8];
        gemm64_8r(xnT, wg_u, bgd, R0, cg, acc);
        __syncthreads();

        // ---- sigmoid * o -> gg, overwrite xnT (same transposed swizzle) ----
        #pragma unroll
        for (int cc = 0; cc < 8; ++cc) {
            const int col = cg * 8 + cc;
            const float osv = osh_s[col];
            float* gb = xnT + col * 512;
            const int sw = (col >> 2) << 1;
            #pragma unroll
            for (int k = 0; k < 4; ++k) {
                float2 p2 = unpack2(acc[k][cc]);
                const float g0 = osv * __fdividef(1.f, 1.f + __expf(-p2.x));
                const float g1 = osv * __fdividef(1.f, 1.f + __expf(-p2.y));
                *reinterpret_cast<unsigned long long*>(gb + ((R0 + 2*k) ^ sw)) =
                    packAB(g0, g1);
            }
        }
        __syncthreads();

        // ---- GEMM2: out = gg @ wo + bo ----
        unsigned long long acc2[4][8];
        gemm64_8r(xnT, wo_u, bod, R0, cg, acc2);

        #pragma unroll
        for (int k = 0; k < 4; ++k) {
            float lo[8], hi[8];
            #pragma unroll
            for (int cc = 0; cc < 8; ++cc) {
                float2 p2 = unpack2(acc2[k][cc]);
                lo[cc] = p2.x; hi[cc] = p2.y;
            }
            const int s0 = S0 + R0 + 2*k;
            float* o0 = out + ((size_t)s0 * R_DIM + r) * CE + cg * 8;
            float* o1 = o0 + (size_t)R_DIM * CE;
            reinterpret_cast<float4*>(o0)[0] = make_float4(lo[0], lo[1], lo[2], lo[3]);
            reinterpret_cast<float4*>(o0)[1] = make_float4(lo[4], lo[5], lo[6], lo[7]);
            reinterpret_cast<float4*>(o1)[0] = make_float4(hi[0], hi[1], hi[2], hi[3]);
            reinterpret_cast<float4*>(o1)[1] = make_float4(hi[4], hi[5], hi[6], hi[7]);
        }
        __syncthreads();
    }
}

extern "C" void kernel_launch(void* const* d_in, const int* in_sizes, int n_in,
                              void* d_out, int out_size)
{
    (void)in_sizes; (void)n_in; (void)out_size;
    const float* m    = (const float*)d_in[0];
    const float* mask = (const float*)d_in[1];
    const float* ln_w = (const float*)d_in[2];
    const float* ln_b = (const float*)d_in[3];
    const float* wq   = (const float*)d_in[4];
    const float* wk   = (const float*)d_in[5];
    const float* wv   = (const float*)d_in[6];
    const float* wg   = (const float*)d_in[7];
    const float* bg   = (const float*)d_in[8];
    const float* wo   = (const float*)d_in[9];
    const float* bo   = (const float*)d_in[10];
    float* out = (float*)d_out;

    cudaFuncSetAttribute(msa_k1,
                         cudaFuncAttributeMaxDynamicSharedMemorySize, (int)SMEM1_BYTES);
    cudaFuncSetAttribute(msa_k2,
                         cudaFuncAttributeMaxDynamicSharedMemorySize, (int)SMEM2_BYTES);

    msa_k1<<<R_DIM, NTHR1, SMEM1_BYTES>>>(m, mask, ln_w, ln_b, wq, wk, wv);
    msa_k2<<<R_DIM, NTHR2, SMEM2_BYTES>>>(m, ln_w, ln_b, wg, bg, wo, bo, out);
}

// round 7
// speedup vs baseline: 1.2959x; 1.1215x over previous
#include <cuda_runtime.h>
#include <cstdint>
#include <cstddef>

namespace {
constexpr int S_DIM = 2048, R_DIM = 384, CE = 64;
// ---- K1 (phases A+C): 512 threads ----
constexpr int NTHR1 = 512, RPT = 4;
constexpr int OFF_WK = 33024, OFF_WV = 33536, OFF_QVEC = 34048, OFF_QH = 34112;
constexpr int OFF_RED = 34176, OFF_MAX = 35328;
constexpr int SMEM1_FL = 35344;
constexpr size_t SMEM1_BYTES = (size_t)SMEM1_FL * 4;
// ---- K2 (phase D): 512 threads, 8x8 register tile ----
constexpr int NTHR2 = 512, CHUNK = 512, NCH = 4;
constexpr int WD = 80;                      // u64 per dup-weight row
constexpr int K2_XNT = 20480;               // fl offset of xnT[64][512]
constexpr int K2_LNW = 53248, K2_LNB = 53312, K2_BGD = 53376, K2_BOD = 53504;
constexpr int K2_OSH = 53632;
constexpr int SMEM2_FL = 53696;
constexpr size_t SMEM2_BYTES = (size_t)SMEM2_FL * 4;
}

__device__ float2 g_stat[(size_t)R_DIM * S_DIM];   // (mu, rstd) per (r, s)
__device__ float  g_osh[(size_t)R_DIM * CE];       // o_flat per column

struct alignas(16) u64x2 { unsigned long long a, b; };

__device__ __forceinline__ unsigned long long pack2(float x) {
    unsigned long long r;
    asm("mov.b64 %0, {%1, %2};" : "=l"(r) : "f"(x), "f"(x));
    return r;
}
__device__ __forceinline__ unsigned long long packAB(float a, float b) {
    unsigned long long r;
    asm("mov.b64 %0, {%1, %2};" : "=l"(r) : "f"(a), "f"(b));
    return r;
}
__device__ __forceinline__ float2 unpack2(unsigned long long v) {
    float2 f;
    asm("mov.b64 {%0, %1}, %2;" : "=f"(f.x), "=f"(f.y) : "l"(v));
    return f;
}
__device__ __forceinline__ void ffma2(unsigned long long& d,
                                      unsigned long long a, unsigned long long b) {
    asm("fma.rn.f32x2 %0, %1, %2, %0;" : "+l"(d) : "l"(a), "l"(b));
}
__device__ __forceinline__ unsigned long long addf2(unsigned long long a,
                                                    unsigned long long b) {
    unsigned long long r;
    asm("add.rn.f32x2 %0, %1, %2;" : "=l"(r) : "l"(a), "l"(b));
    return r;
}

// ===========================================================================
// K1: phase A (LN stats + folded k/v proj + masked qsum) and phase C
// ===========================================================================
__global__ void __launch_bounds__(NTHR1, 1)
msa_k1(const float* __restrict__ m,    const float* __restrict__ mask,
       const float* __restrict__ ln_w, const float* __restrict__ ln_b,
       const float* __restrict__ wq,   const float* __restrict__ wk,
       const float* __restrict__ wv)
{
    extern __shared__ float smf[];
    unsigned long long* kbuf_u = reinterpret_cast<unsigned long long*>(smf);
    unsigned long long* vbuf_u = kbuf_u + 4 * S_DIM;
    float* wkp_s = smf + OFF_WK;     // lnw-folded wk
    float* wvp_s = smf + OFF_WV;     // lnw-folded wv
    float* qvec_s= smf + OFF_QVEC;
    float* qh_s  = smf + OFF_QH;
    float* red   = smf + OFF_RED;
    float* max_sh= smf + OFF_MAX;
    __shared__ float lnw_s[64], lnb_s[64];
    __shared__ __align__(16) float corr[32];  // [0:8)swk [8:16)swv [16:24)kb0 [24:32)vb0

    const int tid  = threadIdx.x;
    const int r    = blockIdx.x;
    const int lane = tid & 31;
    const int wid  = tid >> 5;

    if (tid < 64) { lnw_s[tid] = ln_w[tid]; lnb_s[tid] = ln_b[tid]; }
    __syncthreads();
    for (int i = tid; i < 512; i += NTHR1) {
        const int c = i >> 3;
        wkp_s[i] = lnw_s[c] * __ldg(wk + i);
        wvp_s[i] = lnw_s[c] * __ldg(wv + i);
    }
    if (tid < 32) {
        const int j = tid & 7, kind = tid >> 3;
        float acc = 0.f;
        #pragma unroll 8
        for (int c = 0; c < 64; ++c) {
            const float w = (kind & 1) ? __ldg(wv + c * 8 + j) : __ldg(wk + c * 8 + j);
            const float s = (kind & 2) ? lnb_s[c] : lnw_s[c];
            acc = fmaf(s, w, acc);
        }
        corr[tid] = acc;
    }
    __syncthreads();

    // ---------------- Phase A ----------------
    unsigned long long qsum2[32];
    #pragma unroll
    for (int t = 0; t < 32; ++t) qsum2[t] = 0ull;
    float msum = 0.f, bsum = 0.f;

    #pragma unroll 1
    for (int i = 0; i < RPT; ++i) {
        const int s = tid + NTHR1 * i;
        const float4* xr = reinterpret_cast<const float4*>(m + ((size_t)s * R_DIM + r) * CE);
        // pass 1: stats
        float sum = 0.f, sq = 0.f;
        #pragma unroll
        for (int t = 0; t < 16; ++t) {
            float4 v = __ldg(xr + t);
            sum += v.x + v.y + v.z + v.w;
            sq = fmaf(v.x, v.x, sq); sq = fmaf(v.y, v.y, sq);
            sq = fmaf(v.z, v.z, sq); sq = fmaf(v.w, v.w, sq);
        }
        const float muv  = sum * (1.f / CE);
        const float var  = sq * (1.f / CE) - muv * muv;
        const float rstd = rsqrtf(var + 1e-5f);
        const float mk   = __ldg(mask + (size_t)s * R_DIM + r);
        g_stat[(size_t)r * S_DIM + s] = make_float2(muv, rstd);
        msum += mk;
        const float wA = mk * rstd;
        bsum = fmaf(wA, muv, bsum);
        const unsigned long long wA2 = pack2(wA);

        unsigned long long ka[4], va[4];
        #pragma unroll
        for (int t = 0; t < 4; ++t) { ka[t] = 0ull; va[t] = 0ull; }

        // pass 2 (L1-hot): raw-x projections + A[c] accumulation
        #pragma unroll
        for (int t = 0; t < 16; ++t) {
            float4 v = __ldg(xr + t);
            ffma2(qsum2[2*t],   packAB(v.x, v.y), wA2);
            ffma2(qsum2[2*t+1], packAB(v.z, v.w), wA2);
            const float xv[4] = {v.x, v.y, v.z, v.w};
            #pragma unroll
            for (int j = 0; j < 4; ++j) {
                const int c = 4*t + j;
                const unsigned long long xx = pack2(xv[j]);
                u64x2 k0 = reinterpret_cast<const u64x2*>(wkp_s + c * 8)[0];
                u64x2 v0 = reinterpret_cast<const u64x2*>(wvp_s + c * 8)[0];
                u64x2 k1 = reinterpret_cast<const u64x2*>(wkp_s + c * 8)[1];
                u64x2 v1 = reinterpret_cast<const u64x2*>(wvp_s + c * 8)[1];
                ffma2(ka[0], xx, k0.a); ffma2(ka[1], xx, k0.b);
                ffma2(ka[2], xx, k1.a); ffma2(ka[3], xx, k1.b);
                ffma2(va[0], xx, v0.a); ffma2(va[1], xx, v0.b);
                ffma2(va[2], xx, v1.a); ffma2(va[3], xx, v1.b);
            }
        }
        // epilogue: k = rstd*kacc - (rstd*mu)*swk + kb0  (pairwise)
        const unsigned long long r2  = pack2(rstd);
        const unsigned long long nm2 = pack2(-rstd * muv);
        const unsigned long long* swk2 = reinterpret_cast<const unsigned long long*>(corr);
        const unsigned long long* swv2 = swk2 + 4;
        const unsigned long long* kb02 = swk2 + 8;
        const unsigned long long* vb02 = swk2 + 12;
        #pragma unroll
        for (int t = 0; t < 4; ++t) {
            unsigned long long kacc = kb02[t];
            ffma2(kacc, r2, ka[t]); ffma2(kacc, nm2, swk2[t]);
            kbuf_u[t * S_DIM + s] = kacc;
            unsigned long long vacc = vb02[t];
            ffma2(vacc, r2, va[t]); ffma2(vacc, nm2, swv2[t]);
            vbuf_u[t * S_DIM + s] = vacc;
        }
    }

    #pragma unroll
    for (int t = 0; t < 32; ++t) {
        #pragma unroll
        for (int o = 16; o > 0; o >>= 1)
            qsum2[t] = addf2(qsum2[t], __shfl_xor_sync(0xffffffffu, qsum2[t], o));
    }
    #pragma unroll
    for (int o = 16; o > 0; o >>= 1) {
        msum += __shfl_xor_sync(0xffffffffu, msum, o);
        bsum += __shfl_xor_sync(0xffffffffu, bsum, o);
    }
    if (lane == 0) {
        #pragma unroll
        for (int t = 0; t < 32; ++t) {
            float2 p = unpack2(qsum2[t]);
            red[wid * 72 + 2*t] = p.x; red[wid * 72 + 2*t+1] = p.y;
        }
        red[wid * 72 + 64] = msum;
        red[wid * 72 + 65] = bsum;
    }
    __syncthreads();

    if (tid < 64) {
        float A = 0.f, Ms = 0.f, Bs = 0.f;
        #pragma unroll
        for (int w = 0; w < 16; ++w) {
            A  += red[w * 72 + tid];
            Ms += red[w * 72 + 64];
            Bs += red[w * 72 + 65];
        }
        qvec_s[tid] = (lnw_s[tid] * (A - Bs) + lnb_s[tid] * Ms)
                      * __fdividef(1.f, Ms + 1e-10f);
    }
    __syncthreads();
    if (tid < 64) {
        float acc = 0.f;
        #pragma unroll 8
        for (int c = 0; c < CE; ++c) acc = fmaf(qvec_s[c], __ldg(wq + c * 64 + tid), acc);
        qh_s[tid] = acc * 0.3535533905932738f;
    }
    __syncthreads();

    // ---------------- Phase C ----------------
    float sc[RPT][8], mh[8];
    #pragma unroll
    for (int h = 0; h < 8; ++h) mh[h] = -1e30f;

    #pragma unroll
    for (int i = 0; i < RPT; ++i) {
        const int s = tid + NTHR1 * i;
        unsigned long long kk[4];
        #pragma unroll
        for (int j = 0; j < 4; ++j) kk[j] = kbuf_u[j * S_DIM + s];
        const float bias = 1e9f * (__ldg(mask + (size_t)s * R_DIM + r) - 1.f);
        #pragma unroll
        for (int h = 0; h < 8; ++h) {
            unsigned long long acc = 0ull;
            #pragma unroll
            for (int j = 0; j < 4; ++j) {
                unsigned long long q2 =
                    reinterpret_cast<const unsigned long long*>(qh_s)[h*4+j];
                ffma2(acc, q2, kk[j]);
            }
            float2 p = unpack2(acc);
            float a = bias + p.x + p.y;
            sc[i][h] = a;
            mh[h] = fmaxf(mh[h], a);
        }
    }
    #pragma unroll
    for (int h = 0; h < 8; ++h) {
        #pragma unroll
        for (int o = 16; o > 0; o >>= 1)
            mh[h] = fmaxf(mh[h], __shfl_xor_sync(0xffffffffu, mh[h], o));
    }
    if (lane == 0) {
        #pragma unroll
        for (int h = 0; h < 8; ++h) red[wid * 72 + h] = mh[h];
    }
    __syncthreads();
    if (tid < 8) {
        float mm = -1e30f;
        #pragma unroll
        for (int w = 0; w < 16; ++w) mm = fmaxf(mm, red[w * 72 + tid]);
        max_sh[tid] = mm;
    }
    __syncthreads();

    #pragma unroll 1
    for (int hb = 0; hb < 2; ++hb) {
        unsigned long long oacc2[16];
        float sumh[4];
        #pragma unroll
        for (int t = 0; t < 16; ++t) oacc2[t] = 0ull;
        #pragma unroll
        for (int h = 0; h < 4; ++h) sumh[h] = 0.f;

        #pragma unroll
        for (int i = 0; i < RPT; ++i) {
            const int s = tid + NTHR1 * i;
            unsigned long long vv[4];
            #pragma unroll
            for (int j = 0; j < 4; ++j) vv[j] = vbuf_u[j * S_DIM + s];
            #pragma unroll
            for (int h = 0; h < 4; ++h) {
                const int hh = hb * 4 + h;
                const float e = __expf(sc[i][hh] - max_sh[hh]);
                sumh[h] += e;
                const unsigned long long e2 = pack2(e);
                #pragma unroll
                for (int j = 0; j < 4; ++j) ffma2(oacc2[h*4+j], e2, vv[j]);
            }
        }
        #pragma unroll
        for (int t = 0; t < 16; ++t) {
            #pragma unroll
            for (int o = 16; o > 0; o >>= 1)
                oacc2[t] = addf2(oacc2[t], __shfl_xor_sync(0xffffffffu, oacc2[t], o));
        }
        #pragma unroll
        for (int h = 0; h < 4; ++h) {
            #pragma unroll
            for (int o = 16; o > 0; o >>= 1)
                sumh[h] += __shfl_xor_sync(0xffffffffu, sumh[h], o);
        }
        if (lane == 0) {
            #pragma unroll
            for (int t = 0; t < 16; ++t) {
                float2 p = unpack2(oacc2[t]);
                red[wid * 72 + hb*32 + 2*t]   = p.x;
                red[wid * 72 + hb*32 + 2*t+1] = p.y;
            }
            #pragma unroll
            for (int h = 0; h < 4; ++h) red[wid * 72 + 64 + hb*4 + h] = sumh[h];
        }
        __syncthreads();
    }
    if (tid < 64) {
        float t0 = 0.f, ss = 0.f;
        #pragma unroll
        for (int w = 0; w < 16; ++w) {
            t0 += red[w * 72 + tid];
            ss += red[w * 72 + 64 + (tid >> 3)];
        }
        g_osh[r * CE + tid] = __fdividef(t0, ss);
    }
}

// ===========================================================================
// K2: phase D — 512 threads, 8x8 register tile, all-LDS.128 GEMM
// ===========================================================================
__device__ __forceinline__ void gemm64_8r(const float* __restrict__ xb_base,
                                          const unsigned long long* __restrict__ wtab,
                                          const unsigned long long* __restrict__ bias,
                                          int R0, int cg,
                                          unsigned long long acc[4][8])
{
    #pragma unroll
    for (int k = 0; k < 4; ++k)
        #pragma unroll
        for (int cc = 0; cc < 8; ++cc) acc[k][cc] = bias[cg * 8 + cc];

    #pragma unroll 4
    for (int c4 = 0; c4 < 16; ++c4) {
        const int p = c4 & 3;                       // compile-time in unroll-4 body
        const int base = R0 ^ ((2 * c4) & 24);      // aligned 8-float block
        const float* xcol = xb_base + c4 * 4 * 512 + base;
        const unsigned long long* wr = wtab + c4 * 4 * WD + cg * 10;
        #pragma unroll
        for (int ci = 0; ci < 4; ++ci) {
            u64x2 ua = *reinterpret_cast<const u64x2*>(xcol + ci * 512);
            u64x2 ub = *reinterpret_cast<const u64x2*>(xcol + ci * 512 + 4);
            // row-pair k lives at u64 index k ^ p within {ua.a, ua.b, ub.a, ub.b}
            unsigned long long u0 = ua.a, u1 = ua.b, u2 = ub.a, u3 = ub.b;
            unsigned long long x0 = (p == 0) ? u0 : (p == 1) ? u1 : (p == 2) ? u2 : u3;
            unsigned long long x1 = (p == 0) ? u1 : (p == 1) ? u0 : (p == 2) ? u3 : u2;
            unsigned long long x2 = (p == 0) ? u2 : (p == 1) ? u3 : (p == 2) ? u0 : u1;
            unsigned long long x3 = (p == 0) ? u3 : (p == 1) ? u2 : (p == 2) ? u1 : u0;
            const u64x2* wp = reinterpret_cast<const u64x2*>(wr + ci * WD);
            u64x2 w0 = wp[0], w1 = wp[1], w2 = wp[2], w3 = wp[3];
            ffma2(acc[0][0], x0, w0.a); ffma2(acc[0][1], x0, w0.b);
            ffma2(acc[0][2], x0, w1.a); ffma2(acc[0][3], x0, w1.b);
            ffma2(acc[0][4], x0, w2.a); ffma2(acc[0][5], x0, w2.b);
            ffma2(acc[0][6], x0, w3.a); ffma2(acc[0][7], x0, w3.b);
            ffma2(acc[1][0], x1, w0.a); ffma2(acc[1][1], x1, w0.b);
            ffma2(acc[1][2], x1, w1.a); ffma2(acc[1][3], x1, w1.b);
            ffma2(acc[1][4], x1, w2.a); ffma2(acc[1][5], x1, w2.b);
            ffma2(acc[1][6], x1, w3.a); ffma2(acc[1][7], x1, w3.b);
            ffma2(acc[2][0], x2, w0.a); ffma2(acc[2][1], x2, w0.b);
            ffma2(acc[2][2], x2, w1.a); ffma2(acc[2][3], x2, w1.b);
            ffma2(acc[2][4], x2, w2.a); ffma2(acc[2][5], x2, w2.b);
            ffma2(acc[2][6], x2, w3.a); ffma2(acc[2][7], x2, w3.b);
            ffma2(acc[3][0], x3, w0.a); ffma2(acc[3][1], x3, w0.b);
            ffma2(acc[3][2], x3, w1.a); ffma2(acc[3][3], x3, w1.b);
            ffma2(acc[3][4], x3, w2.a); ffma2(acc[3][5], x3, w2.b);
            ffma2(acc[3][6], x3, w3.a); ffma2(acc[3][7], x3, w3.b);
        }
    }
}

__global__ void __launch_bounds__(NTHR2, 1)
msa_k2(const float* __restrict__ m,    const float* __restrict__ ln_w,
       const float* __restrict__ ln_b, const float* __restrict__ wg,
       const float* __restrict__ bg,   const float* __restrict__ wo,
       const float* __restrict__ bo,   float* __restrict__ out)
{
    extern __shared__ float smf[];
    unsigned long long* wg_u = reinterpret_cast<unsigned long long*>(smf);
    unsigned long long* wo_u = wg_u + 64 * WD;
    float* xnT   = smf + K2_XNT;
    float* lnw_s = smf + K2_LNW;
    float* lnb_s = smf + K2_LNB;
    unsigned long long* bgd = reinterpret_cast<unsigned long long*>(smf + K2_BGD);
    unsigned long long* bod = reinterpret_cast<unsigned long long*>(smf + K2_BOD);
    float* osh_s = smf + K2_OSH;

    const int tid = threadIdx.x;
    const int r   = blockIdx.x;

    // dup-pair weight tables: row c, 8 groups of (8 data + 2 pad) u64
    for (int idx = tid; idx < 4096; idx += NTHR2) {
        const int c = idx >> 6, col = idx & 63;
        const int dst = c * WD + (col >> 3) * 10 + (col & 7);
        wg_u[dst] = pack2(__ldg(wg + idx));
        wo_u[dst] = pack2(__ldg(wo + idx));
    }
    if (tid < 64) {
        lnw_s[tid] = __ldg(ln_w + tid);
        lnb_s[tid] = __ldg(ln_b + tid);
        bgd[tid] = pack2(__ldg(bg + tid));
        bod[tid] = pack2(__ldg(bo + tid));
        osh_s[tid] = g_osh[r * CE + tid];
    }
    __syncthreads();

    const int cg  = tid & 7;
    const int rg  = tid >> 3;        // 0..63
    const int R0  = rg * 8;          // 8 rows per thread, 512-row chunk
    const int c4l = tid & 15;        // loader column-quad
    const int rw0 = tid >> 4;        // loader base row (0..31)
    const float4 lwv = reinterpret_cast<const float4*>(lnw_s)[c4l];
    const float4 lbv = reinterpret_cast<const float4*>(lnb_s)[c4l];

    #pragma unroll 1
    for (int ch = 0; ch < NCH; ++ch) {
        const int S0 = ch * CHUNK;

        // ---- load + normalize chunk into swizzled xnT ----
        #pragma unroll
        for (int k = 0; k < 16; ++k) {
            const int row = rw0 + 32 * k;
            float2 st = __ldg(&g_stat[(size_t)r * S_DIM + S0 + row]);
            float4 v  = __ldg(reinterpret_cast<const float4*>(
                          m + ((size_t)(S0 + row) * R_DIM + r) * CE) + c4l);
            const int rw = row ^ (2 * c4l);
            xnT[(4*c4l+0) * 512 + rw] = (v.x - st.x) * st.y * lwv.x + lbv.x;
            xnT[(4*c4l+1) * 512 + rw] = (v.y - st.x) * st.y * lwv.y + lbv.y;
            xnT[(4*c4l+2) * 512 + rw] = (v.z - st.x) * st.y * lwv.z + lbv.z;
            xnT[(4*c4l+3) * 512 + rw] = (v.w - st.x) * st.y * lwv.w + lbv.w;
        }
        __syncthreads();

        // ---- GEMM1: gate = xn @ wg + bg ----
        unsigned long long acc[4][8];
        gemm64_8r(xnT, wg_u, bgd, R0, cg, acc);
        __syncthreads();

        // ---- sigmoid * o -> gg, overwrite xnT (same transposed swizzle) ----
        #pragma unroll
        for (int cc = 0; cc < 8; ++cc) {
            const int col = cg * 8 + cc;
            const float osv = osh_s[col];
            float* gb = xnT + col * 512;
            const int sw = (col >> 2) << 1;
            #pragma unroll
            for (int k = 0; k < 4; ++k) {
                float2 p2 = unpack2(acc[k][cc]);
                const float g0 = osv * __fdividef(1.f, 1.f + __expf(-p2.x));
                const float g1 = osv * __fdividef(1.f, 1.f + __expf(-p2.y));
                *reinterpret_cast<unsigned long long*>(gb + ((R0 + 2*k) ^ sw)) =
                    packAB(g0, g1);
            }
        }
        __syncthreads();

        // ---- GEMM2: out = gg @ wo + bo ----
        unsigned long long acc2[4][8];
        gemm64_8r(xnT, wo_u, bod, R0, cg, acc2);

        #pragma unroll
        for (int k = 0; k < 4; ++k) {
            float lo[8], hi[8];
            #pragma unroll
            for (int cc = 0; cc < 8; ++cc) {
                float2 p2 = unpack2(acc2[k][cc]);
                lo[cc] = p2.x; hi[cc] = p2.y;
            }
            const int s0 = S0 + R0 + 2*k;
            float* o0 = out + ((size_t)s0 * R_DIM + r) * CE + cg * 8;
            float* o1 = o0 + (size_t)R_DIM * CE;
            reinterpret_cast<float4*>(o0)[0] = make_float4(lo[0], lo[1], lo[2], lo[3]);
            reinterpret_cast<float4*>(o0)[1] = make_float4(lo[4], lo[5], lo[6], lo[7]);
            reinterpret_cast<float4*>(o1)[0] = make_float4(hi[0], hi[1], hi[2], hi[3]);
            reinterpret_cast<float4*>(o1)[1] = make_float4(hi[4], hi[5], hi[6], hi[7]);
        }
        __syncthreads();
    }
}

extern "C" void kernel_launch(void* const* d_in, const int* in_sizes, int n_in,
                              void* d_out, int out_size)
{
    (void)in_sizes; (void)n_in; (void)out_size;
    const float* m    = (const float*)d_in[0];
    const float* mask = (const float*)d_in[1];
    const float* ln_w = (const float*)d_in[2];
    const float* ln_b = (const float*)d_in[3];
    const float* wq   = (const float*)d_in[4];
    const float* wk   = (const float*)d_in[5];
    const float* wv   = (const float*)d_in[6];
    const float* wg   = (const float*)d_in[7];
    const float* bg   = (const float*)d_in[8];
    const float* wo   = (const float*)d_in[9];
    const float* bo   = (const float*)d_in[10];
    float* out = (float*)d_out;

    cudaFuncSetAttribute(msa_k1,
                         cudaFuncAttributeMaxDynamicSharedMemorySize, (int)SMEM1_BYTES);
    cudaFuncSetAttribute(msa_k2,
                         cudaFuncAttributeMaxDynamicSharedMemorySize, (int)SMEM2_BYTES);

    msa_k1<<<R_DIM, NTHR1, SMEM1_BYTES>>>(m, mask, ln_w, ln_b, wq, wk, wv);
    msa_k2<<<R_DIM, NTHR2, SMEM2_BYTES>>>(m, ln_w, ln_b, wg, bg, wo, bo, out);
}